// round 15
// baseline (speedup 1.0000x reference)
#include <cuda_runtime.h>
#include <cuda_fp16.h>
#include <math.h>
#include <stdint.h>

#define Vv  32000
#define Ee  512
#define Hh  512
#define Bb  16
#define Ss  128
#define G4  2048   // 4*H
#define MBr 2048   // S*B rows

// ---------------- scratch (static device memory; no allocation) ----------------
__device__ __half g_x0h[(size_t)MBr * Ee];        // layer0 input (fp16)
__device__ __half g_x1h[(size_t)MBr * 1024];      // layer1 input (fp16)
__device__ float  g_xg[2][(size_t)MBr * G4];      // per-dir gate preacts (fp32)
__device__ __half g_hh[2][2][Bb * Hh];            // [parity][dir][b*H] (fp16)
__device__ __half g_hfinh[(size_t)Bb * Ss * 1024];// layer1 output (fp16)
__device__ float  g_bias[4096];                   // combined bih+bhh (both dirs)
__device__ unsigned g_flags[2][16][32];           // per-block step flags, 128B lines

// ================= helpers =================
__device__ __forceinline__ uint32_t smem_u32(const void* p) {
    uint32_t a;
    asm("{ .reg .u64 t; cvta.to.shared.u64 t, %1; cvt.u32.u64 %0, t; }" : "=r"(a) : "l"(p));
    return a;
}
__device__ __forceinline__ void cp16(uint32_t dst, const void* src) {
    asm volatile("cp.async.cg.shared.global [%0], [%1], 16;" :: "r"(dst), "l"(src) : "memory");
}
__device__ __forceinline__ void ldsm_x4(uint32_t* r, uint32_t addr) {
    asm volatile("ldmatrix.sync.aligned.m8n8.x4.shared.b16 {%0,%1,%2,%3}, [%4];"
                 : "=r"(r[0]), "=r"(r[1]), "=r"(r[2]), "=r"(r[3]) : "r"(addr));
}
__device__ __forceinline__ void mma_f16(float* c, const uint32_t* a, uint32_t b0, uint32_t b1) {
    asm volatile(
        "mma.sync.aligned.m16n8k16.row.col.f32.f16.f16.f32 "
        "{%0,%1,%2,%3}, {%4,%5,%6,%7}, {%8,%9}, {%0,%1,%2,%3};\n"
        : "+f"(c[0]), "+f"(c[1]), "+f"(c[2]), "+f"(c[3])
        : "r"(a[0]), "r"(a[1]), "r"(a[2]), "r"(a[3]), "r"(b0), "r"(b1));
}
__device__ __forceinline__ unsigned ld_acq(unsigned* p) {
    unsigned v;
    asm volatile("ld.acquire.gpu.global.u32 %0, [%1];" : "=r"(v) : "l"(p) : "memory");
    return v;
}

// ================= fp16 mma GEMM with fused fp32->fp16 B conversion =================
#define RSTR 80                    // bytes per smem row (32 halves + 8 pad)
#define ASTG (128 * RSTR)          // 10240 per A stage
#define BBASE (3 * ASTG)           // B stages start at 30720
#define GEMM_DSM 67584             // max(6*10240=61440, epilogue 128*132*4=67584)

__global__ __launch_bounds__(256, 2) void gemm_mma(
    const __half* __restrict__ A,
    const float* __restrict__ Bf32a, const float* __restrict__ Bf32b,
    const float* __restrict__ bias, float* __restrict__ out,
    int Kdim, int mode)
{
    extern __shared__ char dsmc[];
    float* dsm = reinterpret_cast<float*>(dsmc);
    int tid = threadIdx.x, wid = tid >> 5, lane = tid & 31;
    int warp_m = wid & 1, warp_n = wid >> 1;
    int gr = lane >> 2, gc = lane & 3;
    int m0 = blockIdx.x << 7;
    int n0 = blockIdx.y << 7;
    uint32_t base = smem_u32(dsmc);
    int KC = Kdim >> 5;

    const __half* Ag = A + (size_t)m0 * Kdim;
    const float* Bg = (mode == 0 && n0 >= 2048)
                    ? Bf32b + (size_t)(n0 - 2048) * Kdim
                    : Bf32a + (size_t)n0 * Kdim;

    int brow0 = tid >> 3, bg = tid & 7;
    const float* Bp = Bg + (size_t)brow0 * Kdim + bg * 4;

    uint32_t aoff = (uint32_t)((lane & 15) * RSTR + (lane >> 4) * 16)
                  + (uint32_t)(warp_m * 64 * RSTR);
    uint32_t boff = (uint32_t)(((lane & 7) + ((lane >> 3) & 1) * 8) * RSTR + (lane >> 4) * 16)
                  + (uint32_t)(warp_n * 32 * RSTR);

    float acc[4][4][4];
#pragma unroll
    for (int mi = 0; mi < 4; mi++)
#pragma unroll
        for (int ni = 0; ni < 4; ni++)
#pragma unroll
            for (int q = 0; q < 4; q++) acc[mi][ni][q] = 0.f;

#define LOAD_A(s, c) do {                                                   \
        uint32_t sb_ = base + (s) * ASTG;                                   \
        const __half* Ac_ = Ag + (c) * 32;                                  \
        _Pragma("unroll")                                                   \
        for (int q_ = 0; q_ < 2; q_++) {                                    \
            int f_ = q_ * 256 + tid;                                        \
            int row_ = f_ >> 2, g_ = f_ & 3;                                \
            cp16(sb_ + row_ * RSTR + g_ * 16,                               \
                 Ac_ + (size_t)row_ * Kdim + g_ * 8);                       \
        }                                                                   \
        asm volatile("cp.async.commit_group;" ::: "memory");                \
    } while (0)

#define STS_B(s, v) do {                                                    \
        char* bs_ = dsmc + BBASE + (s) * ASTG;                              \
        _Pragma("unroll")                                                   \
        for (int k_ = 0; k_ < 4; k_++) {                                    \
            __half2* d_ = reinterpret_cast<__half2*>(                       \
                bs_ + (brow0 + k_ * 32) * RSTR + bg * 8);                   \
            d_[0] = __floats2half2_rn((v)[k_].x, (v)[k_].y);                \
            d_[1] = __floats2half2_rn((v)[k_].z, (v)[k_].w);                \
        }                                                                   \
    } while (0)

#define LDG_B(c, v) do {                                                    \
        const float* p_ = Bp + (c) * 32;                                    \
        _Pragma("unroll")                                                   \
        for (int k_ = 0; k_ < 4; k_++)                                      \
            (v)[k_] = *reinterpret_cast<const float4*>(p_ + (size_t)(k_ * 32) * Kdim); \
    } while (0)

    LOAD_A(0, 0);
    LOAD_A(1, 1);
    LOAD_A(2, 2);
    {
        float4 v[4];
#pragma unroll
        for (int c = 0; c < 3; c++) { LDG_B(c, v); STS_B(c, v); }
    }
    float4 bb[4];
    LDG_B(3, bb);

    int s = 0;
    for (int c = 0; c < KC; c++) {
        asm volatile("cp.async.wait_group 2;" ::: "memory");
        __syncthreads();
        uint32_t sa = base + s * ASTG;
        uint32_t sb = base + BBASE + s * ASTG;
#pragma unroll
        for (int kb = 0; kb < 64; kb += 32) {
            uint32_t af[4][4], bf[2][4];
#pragma unroll
            for (int mi = 0; mi < 4; mi++)
                ldsm_x4(af[mi], sa + aoff + (uint32_t)(mi * 16 * RSTR) + kb);
#pragma unroll
            for (int nj = 0; nj < 2; nj++)
                ldsm_x4(bf[nj], sb + boff + (uint32_t)(nj * 16 * RSTR) + kb);
#pragma unroll
            for (int mi = 0; mi < 4; mi++)
#pragma unroll
                for (int ni = 0; ni < 4; ni++)
                    mma_f16(acc[mi][ni], af[mi],
                            bf[ni >> 1][ni & 1], bf[ni >> 1][2 + (ni & 1)]);
        }
        __syncthreads();
        if (c + 3 < KC) {
            STS_B(s, bb);
            if (c + 4 < KC) LDG_B(c + 4, bb);
            LOAD_A(s, c + 3);
        } else {
            asm volatile("cp.async.commit_group;" ::: "memory");
        }
        s++; if (s == 3) s = 0;
    }
    asm volatile("cp.async.wait_group 0;" ::: "memory");
    __syncthreads();

    if (mode == 1) {
        float* es = dsm;  // 128 cols x stride 132
#pragma unroll
        for (int mi = 0; mi < 4; mi++) {
            int row = warp_m * 64 + mi * 16 + gr;
#pragma unroll
            for (int ni = 0; ni < 4; ni++) {
                int col = warp_n * 32 + ni * 8 + gc * 2;
                es[col * 132 + row]           = acc[mi][ni][0];
                es[(col + 1) * 132 + row]     = acc[mi][ni][1];
                es[col * 132 + row + 8]       = acc[mi][ni][2];
                es[(col + 1) * 132 + row + 8] = acc[mi][ni][3];
            }
        }
        __syncthreads();
        int bb2 = blockIdx.x;
        float* ob = out + (size_t)bb2 * Vv * Ss;
#pragma unroll 4
        for (int i = 0; i < 16; i++) {
            int f4 = i * 256 + tid;
            int rown = f4 >> 5;
            int c4 = f4 & 31;
            float4 v = *reinterpret_cast<const float4*>(es + rown * 132 + c4 * 4);
            float bv = bias[n0 + rown];
            v.x += bv; v.y += bv; v.z += bv; v.w += bv;
            *reinterpret_cast<float4*>(ob + (size_t)(n0 + rown) * Ss + c4 * 4) = v;
        }
    } else {
        int dirq = n0 >> 11;
        float* dst = out + (size_t)dirq * ((size_t)MBr * G4);
        int ncol0 = n0 & 2047;
#pragma unroll
        for (int mi = 0; mi < 4; mi++) {
            int row = m0 + warp_m * 64 + mi * 16 + gr;
#pragma unroll
            for (int ni = 0; ni < 4; ni++) {
                int nglob = n0 + warp_n * 32 + ni * 8 + gc * 2;
                int col = ncol0 + warp_n * 32 + ni * 8 + gc * 2;
                float bv0 = bias[nglob], bv1 = bias[nglob + 1];
                float2 v0 = make_float2(acc[mi][ni][0] + bv0, acc[mi][ni][1] + bv1);
                float2 v1 = make_float2(acc[mi][ni][2] + bv0, acc[mi][ni][3] + bv1);
                *reinterpret_cast<float2*>(dst + (size_t)row * G4 + col) = v0;
                *reinterpret_cast<float2*>(dst + (size_t)(row + 8) * G4 + col) = v1;
            }
        }
    }
#undef LOAD_A
#undef STS_B
#undef LDG_B
}

// ---------------- combined bias ----------------
__global__ void bias_comb(const float* __restrict__ b1f, const float* __restrict__ b2f,
                          const float* __restrict__ b1b, const float* __restrict__ b2b) {
    int i = blockIdx.x * blockDim.x + threadIdx.x;
    g_bias[i] = b1f[i] + b2f[i];
    g_bias[2048 + i] = b1b[i] + b2b[i];
}

// ---------------- embedding gather (fp16 out) ----------------
__global__ void embed_kernel(const int* __restrict__ tok, const float* __restrict__ ew) {
    int sb = blockIdx.x;
    int s = sb >> 4, b = sb & 15;
    int t = tok[b * Ss + s];
    float4 v = reinterpret_cast<const float4*>(ew + (size_t)t * Ee)[threadIdx.x];
    __half2* dst = reinterpret_cast<__half2*>(g_x0h + (size_t)sb * Ee);
    dst[2 * threadIdx.x]     = __floats2half2_rn(v.x, v.y);
    dst[2 * threadIdx.x + 1] = __floats2half2_rn(v.z, v.w);
}

// ================= persistent LSTM: 16 blocks/dir, 512 thr, mma recurrence ==========
// Block handles 32 units (4 gates x 32 = 128 gate-rows). Warp w: gate w>>2, octet w&3.
#define WS16_B (128 * 520 * 2)             // 133120
#define HS16_B (16 * 520 * 2)              // 16640
#define ZR_OFF (WS16_B + HS16_B)           // 149760
#define LSTM_DSM (ZR_OFF + 128 * 16 * 4)   // 157952

__global__ __launch_bounds__(512) void lstm_persist(
    const float* __restrict__ Whh_f, const float* __restrict__ Whh_b, int mode)
{
    extern __shared__ char sm[];
    __half* ws16 = reinterpret_cast<__half*>(sm);
    float* zr = reinterpret_cast<float*>(sm + ZR_OFF);
    int dir = blockIdx.y;
    int u0 = blockIdx.x << 5;
    int tid = threadIdx.x;
    int wid = tid >> 5, lane = tid & 31;
    int gr = lane >> 2, gc = lane & 3;
    int gb = tid >> 5, gu = tid & 31;          // gate thread <-> (batch, unit)
    const float* Whh = dir ? Whh_b : Whh_f;
    uint32_t ws_b = smem_u32(sm);
    uint32_t hs_b = ws_b + WS16_B;

    // stage Whh chunk (fp32->fp16): local row r = gate*32 + ui
    for (int f4 = tid; f4 < 128 * 128; f4 += 512) {
        int r = f4 >> 7, c4 = f4 & 127;
        int R = (r >> 5) * Hh + u0 + (r & 31);
        float4 v = *reinterpret_cast<const float4*>(Whh + (size_t)R * Hh + (c4 << 2));
        __half2* d = reinterpret_cast<__half2*>(ws16 + r * 520 + (c4 << 2));
        d[0] = __floats2half2_rn(v.x, v.y);
        d[1] = __floats2half2_rn(v.z, v.w);
    }
    __syncthreads();

    // B-fragments for this warp's 8 gate-rows, all K=512
    uint32_t wreg[16][4];
    {
        int rl = (wid >> 2) * 32 + (wid & 3) * 8 + (lane & 7);
        uint32_t wrow = ws_b + (uint32_t)(rl * 1040 + (lane >> 3) * 16);
#pragma unroll
        for (int ks = 0; ks < 16; ks++)
            ldsm_x4(wreg[ks], wrow + (uint32_t)(ks * 64));
    }
    __syncthreads();

    uint32_t a_base = hs_b + (uint32_t)((lane & 15) * 1040 + (lane >> 4) * 16);
    float creg = 0.f;
    unsigned fbase = g_flags[dir][blockIdx.x][0];
    int zrow = (wid >> 2) * 32 + (wid & 3) * 8 + 2 * gc;

    for (int t = 0; t < Ss; t++) {
        int tidx = dir ? (Ss - 1 - t) : t;

        // prefetch xg for this step (overlaps the barrier wait below)
        const float* xgd = g_xg[dir] + (size_t)(tidx * Bb + gb) * G4 + (u0 + gu);
        float x0 = xgd[0], x1 = xgd[Hh], x2 = xgd[2 * Hh], x3 = xgd[3 * Hh];

        // wait: all 16 blocks of this dir finished step t-1
        if (t > 0) {
            if (wid == 0) {
                unsigned tgt = fbase + (unsigned)t;
                bool ok;
                do {
                    unsigned a = (lane < 16) ? ld_acq(&g_flags[dir][lane][0]) : tgt;
                    ok = ((int)(a - tgt) >= 0);
                } while (__ballot_sync(0xffffffffu, ok) != 0xffffffffu);
            }
            __syncthreads();
        }

        // stage h(t-1): 16 rows x 64 uint4 = 1024 uint4
        {
            uint4* dst4 = reinterpret_cast<uint4*>(sm + WS16_B);
            if (t == 0) {
                uint4 z = make_uint4(0, 0, 0, 0);
#pragma unroll
                for (int jj = 0; jj < 2; jj++) {
                    int f = jj * 512 + tid;
                    dst4[(f >> 6) * 65 + (f & 63)] = z;
                }
            } else {
                const uint4* src4 = reinterpret_cast<const uint4*>(g_hh[t & 1][dir]);
#pragma unroll
                for (int jj = 0; jj < 2; jj++) {
                    int f = jj * 512 + tid;
                    dst4[(f >> 6) * 65 + (f & 63)] = __ldcv(src4 + f);
                }
            }
        }
        __syncthreads();

        // z = h @ Whh^T : two independent 16-deep mma chains
        float acc0[4] = {0.f, 0.f, 0.f, 0.f};
        float acc1[4] = {0.f, 0.f, 0.f, 0.f};
#pragma unroll
        for (int ks = 0; ks < 32; ks += 2) {
            uint32_t af[4], af2[4];
            ldsm_x4(af, a_base + (uint32_t)(ks * 32));
            mma_f16(acc0, af, wreg[ks >> 1][0], wreg[ks >> 1][1]);
            ldsm_x4(af2, a_base + (uint32_t)((ks + 1) * 32));
            mma_f16(acc1, af2, wreg[ks >> 1][2], wreg[ks >> 1][3]);
        }
        zr[zrow * 16 + gr]           = acc0[0] + acc1[0];
        zr[(zrow + 1) * 16 + gr]     = acc0[1] + acc1[1];
        zr[zrow * 16 + gr + 8]       = acc0[2] + acc1[2];
        zr[(zrow + 1) * 16 + gr + 8] = acc0[3] + acc1[3];
        __syncthreads();

        // gates: thread <-> (b=gb, unit=u0+gu)
        __half hh;
        {
            float zi = zr[(gu) * 16 + gb]      + x0;
            float zf = zr[(32 + gu) * 16 + gb] + x1;
            float zg = zr[(64 + gu) * 16 + gb] + x2;
            float zo = zr[(96 + gu) * 16 + gb] + x3;
            float ig = 1.f / (1.f + expf(-zi));
            float fg = 1.f / (1.f + expf(-zf));
            float gg = tanhf(zg);
            float og = 1.f / (1.f + expf(-zo));
            creg = fg * creg + ig * gg;
            float h = og * tanhf(creg);
            hh = __float2half_rn(h);
            g_hh[(t & 1) ^ 1][dir][gb * Hh + u0 + gu] = hh;
        }
        __syncthreads();

        // release
        if (tid == 0)
            asm volatile("st.release.gpu.global.u32 [%0], %1;"
                         :: "l"(&g_flags[dir][blockIdx.x][0]),
                            "r"(fbase + (unsigned)(t + 1)) : "memory");

        // layer-output store (off critical path)
        if (mode == 0)
            g_x1h[(size_t)(tidx * Bb + gb) * 1024 + (dir << 9) + u0 + gu] = hh;
        else
            g_hfinh[(size_t)gb * (Ss * 1024) + tidx * 1024 + (dir << 9) + u0 + gu] = hh;
    }
}

// ---------------- launch ----------------
extern "C" void kernel_launch(void* const* d_in, const int* in_sizes, int n_in,
                              void* d_out, int out_size)
{
    const int*   tok  = (const int*)d_in[0];
    const float* ew   = (const float*)d_in[1];
    const float* Wih0f = (const float*)d_in[2],  *Whh0f = (const float*)d_in[3];
    const float* bih0f = (const float*)d_in[4],  *bhh0f = (const float*)d_in[5];
    const float* Wih0b = (const float*)d_in[6],  *Whh0b = (const float*)d_in[7];
    const float* bih0b = (const float*)d_in[8],  *bhh0b = (const float*)d_in[9];
    const float* Wih1f = (const float*)d_in[10], *Whh1f = (const float*)d_in[11];
    const float* bih1f = (const float*)d_in[12], *bhh1f = (const float*)d_in[13];
    const float* Wih1b = (const float*)d_in[14], *Whh1b = (const float*)d_in[15];
    const float* bih1b = (const float*)d_in[16], *bhh1b = (const float*)d_in[17];
    const float* linw = (const float*)d_in[18],  *linb  = (const float*)d_in[19];
    float* out = (float*)d_out;

    __half *px0, *px1, *phf;
    float *pxg, *pbias;
    cudaGetSymbolAddress((void**)&px0, g_x0h);
    cudaGetSymbolAddress((void**)&px1, g_x1h);
    cudaGetSymbolAddress((void**)&pxg, g_xg);
    cudaGetSymbolAddress((void**)&phf, g_hfinh);
    cudaGetSymbolAddress((void**)&pbias, g_bias);

    cudaFuncSetAttribute(gemm_mma, cudaFuncAttributeMaxDynamicSharedMemorySize, GEMM_DSM);
    cudaFuncSetAttribute(lstm_persist, cudaFuncAttributeMaxDynamicSharedMemorySize, LSTM_DSM);

    embed_kernel<<<MBr, 128>>>(tok, ew);

    // ---- layer 0 ----
    bias_comb<<<8, 256>>>(bih0f, bhh0f, bih0b, bhh0b);
    gemm_mma<<<dim3(16, 32), 256, GEMM_DSM>>>(px0, Wih0f, Wih0b, pbias, pxg, 512, 0);
    lstm_persist<<<dim3(16, 2), 512, LSTM_DSM>>>(Whh0f, Whh0b, 0);

    // ---- layer 1 ----
    bias_comb<<<8, 256>>>(bih1f, bhh1f, bih1b, bhh1b);
    gemm_mma<<<dim3(16, 32), 256, GEMM_DSM>>>(px1, Wih1f, Wih1b, pbias, pxg, 1024, 0);
    lstm_persist<<<dim3(16, 2), 512, LSTM_DSM>>>(Whh1f, Whh1b, 1);

    // ---- final projection (lin_w fp32 read directly) ----
    gemm_mma<<<dim3(16, 250), 256, GEMM_DSM>>>(phf, linw, linw, linb, out, 1024, 1);
}

// round 16
// speedup vs baseline: 1.1985x; 1.1985x over previous
#include <cuda_runtime.h>
#include <cuda_fp16.h>
#include <math.h>
#include <stdint.h>

#define Vv  32000
#define Ee  512
#define Hh  512
#define Bb  16
#define Ss  128
#define G4  2048   // 4*H
#define MBr 2048   // S*B rows

// ---------------- scratch (static device memory; no allocation) ----------------
__device__ __half g_x0h[(size_t)MBr * Ee];        // layer0 input (fp16)
__device__ __half g_x1h[(size_t)MBr * 1024];      // layer1 input (fp16)
__device__ float  g_xg[2][(size_t)MBr * G4];      // per-dir gate preacts (fp32)
__device__ __half g_hh[2][2][Bb * Hh];            // [parity][dir][b*H] (fp16)
__device__ __half g_hfinh[(size_t)Bb * Ss * 1024];// layer1 output (fp16)
__device__ float  g_bias2[2][4096];               // combined bih+bhh per layer
__device__ unsigned g_flags[2][32][32];           // per-block step flags, 128B lines

// ================= helpers =================
__device__ __forceinline__ uint32_t smem_u32(const void* p) {
    uint32_t a;
    asm("{ .reg .u64 t; cvta.to.shared.u64 t, %1; cvt.u32.u64 %0, t; }" : "=r"(a) : "l"(p));
    return a;
}
__device__ __forceinline__ void cp16(uint32_t dst, const void* src) {
    asm volatile("cp.async.cg.shared.global [%0], [%1], 16;" :: "r"(dst), "l"(src) : "memory");
}
__device__ __forceinline__ void ldsm_x4(uint32_t* r, uint32_t addr) {
    asm volatile("ldmatrix.sync.aligned.m8n8.x4.shared.b16 {%0,%1,%2,%3}, [%4];"
                 : "=r"(r[0]), "=r"(r[1]), "=r"(r[2]), "=r"(r[3]) : "r"(addr));
}
__device__ __forceinline__ void mma_f16(float* c, const uint32_t* a, uint32_t b0, uint32_t b1) {
    asm volatile(
        "mma.sync.aligned.m16n8k16.row.col.f32.f16.f16.f32 "
        "{%0,%1,%2,%3}, {%4,%5,%6,%7}, {%8,%9}, {%0,%1,%2,%3};\n"
        : "+f"(c[0]), "+f"(c[1]), "+f"(c[2]), "+f"(c[3])
        : "r"(a[0]), "r"(a[1]), "r"(a[2]), "r"(a[3]), "r"(b0), "r"(b1));
}
__device__ __forceinline__ unsigned ld_acq(unsigned* p) {
    unsigned v;
    asm volatile("ld.acquire.gpu.global.u32 %0, [%1];" : "=r"(v) : "l"(p) : "memory");
    return v;
}

// ================= fp16 mma GEMM with fused fp32->fp16 B conversion =================
#define RSTR 80                    // bytes per smem row (32 halves + 8 pad)
#define ASTG (128 * RSTR)          // 10240 per A stage
#define BBASE (3 * ASTG)           // B stages start at 30720
#define GEMM_DSM 67584             // max(6*10240=61440, epilogue 128*132*4=67584)

__global__ __launch_bounds__(256, 2) void gemm_mma(
    const __half* __restrict__ A,
    const float* __restrict__ Bf32a, const float* __restrict__ Bf32b,
    const float* __restrict__ bias, float* __restrict__ out,
    int Kdim, int mode)
{
    extern __shared__ char dsmc[];
    float* dsm = reinterpret_cast<float*>(dsmc);
    int tid = threadIdx.x, wid = tid >> 5, lane = tid & 31;
    int warp_m = wid & 1, warp_n = wid >> 1;
    int gr = lane >> 2, gc = lane & 3;
    int m0 = blockIdx.x << 7;
    int n0 = blockIdx.y << 7;
    uint32_t base = smem_u32(dsmc);
    int KC = Kdim >> 5;

    const __half* Ag = A + (size_t)m0 * Kdim;
    const float* Bg = (mode == 0 && n0 >= 2048)
                    ? Bf32b + (size_t)(n0 - 2048) * Kdim
                    : Bf32a + (size_t)n0 * Kdim;

    int brow0 = tid >> 3, bg = tid & 7;
    const float* Bp = Bg + (size_t)brow0 * Kdim + bg * 4;

    uint32_t aoff = (uint32_t)((lane & 15) * RSTR + (lane >> 4) * 16)
                  + (uint32_t)(warp_m * 64 * RSTR);
    uint32_t boff = (uint32_t)(((lane & 7) + ((lane >> 3) & 1) * 8) * RSTR + (lane >> 4) * 16)
                  + (uint32_t)(warp_n * 32 * RSTR);

    float acc[4][4][4];
#pragma unroll
    for (int mi = 0; mi < 4; mi++)
#pragma unroll
        for (int ni = 0; ni < 4; ni++)
#pragma unroll
            for (int q = 0; q < 4; q++) acc[mi][ni][q] = 0.f;

#define LOAD_A(s, c) do {                                                   \
        uint32_t sb_ = base + (s) * ASTG;                                   \
        const __half* Ac_ = Ag + (c) * 32;                                  \
        _Pragma("unroll")                                                   \
        for (int q_ = 0; q_ < 2; q_++) {                                    \
            int f_ = q_ * 256 + tid;                                        \
            int row_ = f_ >> 2, g_ = f_ & 3;                                \
            cp16(sb_ + row_ * RSTR + g_ * 16,                               \
                 Ac_ + (size_t)row_ * Kdim + g_ * 8);                       \
        }                                                                   \
        asm volatile("cp.async.commit_group;" ::: "memory");                \
    } while (0)

#define STS_B(s, v) do {                                                    \
        char* bs_ = dsmc + BBASE + (s) * ASTG;                              \
        _Pragma("unroll")                                                   \
        for (int k_ = 0; k_ < 4; k_++) {                                    \
            __half2* d_ = reinterpret_cast<__half2*>(                       \
                bs_ + (brow0 + k_ * 32) * RSTR + bg * 8);                   \
            d_[0] = __floats2half2_rn((v)[k_].x, (v)[k_].y);                \
            d_[1] = __floats2half2_rn((v)[k_].z, (v)[k_].w);                \
        }                                                                   \
    } while (0)

#define LDG_B(c, v) do {                                                    \
        const float* p_ = Bp + (c) * 32;                                    \
        _Pragma("unroll")                                                   \
        for (int k_ = 0; k_ < 4; k_++)                                      \
            (v)[k_] = *reinterpret_cast<const float4*>(p_ + (size_t)(k_ * 32) * Kdim); \
    } while (0)

    LOAD_A(0, 0);
    LOAD_A(1, 1);
    LOAD_A(2, 2);
    {
        float4 v[4];
#pragma unroll
        for (int c = 0; c < 3; c++) { LDG_B(c, v); STS_B(c, v); }
    }
    float4 bb[4];
    LDG_B(3, bb);

    int s = 0;
    for (int c = 0; c < KC; c++) {
        asm volatile("cp.async.wait_group 2;" ::: "memory");
        __syncthreads();
        uint32_t sa = base + s * ASTG;
        uint32_t sb = base + BBASE + s * ASTG;
#pragma unroll
        for (int kb = 0; kb < 64; kb += 32) {
            uint32_t af[4][4], bf[2][4];
#pragma unroll
            for (int mi = 0; mi < 4; mi++)
                ldsm_x4(af[mi], sa + aoff + (uint32_t)(mi * 16 * RSTR) + kb);
#pragma unroll
            for (int nj = 0; nj < 2; nj++)
                ldsm_x4(bf[nj], sb + boff + (uint32_t)(nj * 16 * RSTR) + kb);
#pragma unroll
            for (int mi = 0; mi < 4; mi++)
#pragma unroll
                for (int ni = 0; ni < 4; ni++)
                    mma_f16(acc[mi][ni], af[mi],
                            bf[ni >> 1][ni & 1], bf[ni >> 1][2 + (ni & 1)]);
        }
        __syncthreads();
        if (c + 3 < KC) {
            STS_B(s, bb);
            if (c + 4 < KC) LDG_B(c + 4, bb);
            LOAD_A(s, c + 3);
        } else {
            asm volatile("cp.async.commit_group;" ::: "memory");
        }
        s++; if (s == 3) s = 0;
    }
    asm volatile("cp.async.wait_group 0;" ::: "memory");
    __syncthreads();

    if (mode == 1) {
        float* es = dsm;  // 128 cols x stride 132
#pragma unroll
        for (int mi = 0; mi < 4; mi++) {
            int row = warp_m * 64 + mi * 16 + gr;
#pragma unroll
            for (int ni = 0; ni < 4; ni++) {
                int col = warp_n * 32 + ni * 8 + gc * 2;
                es[col * 132 + row]           = acc[mi][ni][0];
                es[(col + 1) * 132 + row]     = acc[mi][ni][1];
                es[col * 132 + row + 8]       = acc[mi][ni][2];
                es[(col + 1) * 132 + row + 8] = acc[mi][ni][3];
            }
        }
        __syncthreads();
        int bb2 = blockIdx.x;
        float* ob = out + (size_t)bb2 * Vv * Ss;
#pragma unroll 4
        for (int i = 0; i < 16; i++) {
            int f4 = i * 256 + tid;
            int rown = f4 >> 5;
            int c4 = f4 & 31;
            float4 v = *reinterpret_cast<const float4*>(es + rown * 132 + c4 * 4);
            float bv = bias[n0 + rown];
            v.x += bv; v.y += bv; v.z += bv; v.w += bv;
            *reinterpret_cast<float4*>(ob + (size_t)(n0 + rown) * Ss + c4 * 4) = v;
        }
    } else {
        int dirq = n0 >> 11;
        float* dst = out + (size_t)dirq * ((size_t)MBr * G4);
        int ncol0 = n0 & 2047;
#pragma unroll
        for (int mi = 0; mi < 4; mi++) {
            int row = m0 + warp_m * 64 + mi * 16 + gr;
#pragma unroll
            for (int ni = 0; ni < 4; ni++) {
                int nglob = n0 + warp_n * 32 + ni * 8 + gc * 2;
                int col = ncol0 + warp_n * 32 + ni * 8 + gc * 2;
                float bv0 = bias[nglob], bv1 = bias[nglob + 1];
                float2 v0 = make_float2(acc[mi][ni][0] + bv0, acc[mi][ni][1] + bv1);
                float2 v1 = make_float2(acc[mi][ni][2] + bv0, acc[mi][ni][3] + bv1);
                *reinterpret_cast<float2*>(dst + (size_t)row * G4 + col) = v0;
                *reinterpret_cast<float2*>(dst + (size_t)(row + 8) * G4 + col) = v1;
            }
        }
    }
#undef LOAD_A
#undef STS_B
#undef LDG_B
}

// ---------------- combined bias, both layers in one launch ----------------
__global__ void bias_comb2(const float* __restrict__ b0f1, const float* __restrict__ b0f2,
                           const float* __restrict__ b0b1, const float* __restrict__ b0b2,
                           const float* __restrict__ b1f1, const float* __restrict__ b1f2,
                           const float* __restrict__ b1b1, const float* __restrict__ b1b2) {
    int i = blockIdx.x * blockDim.x + threadIdx.x;   // 0..2047
    g_bias2[0][i]        = b0f1[i] + b0f2[i];
    g_bias2[0][2048 + i] = b0b1[i] + b0b2[i];
    g_bias2[1][i]        = b1f1[i] + b1f2[i];
    g_bias2[1][2048 + i] = b1b1[i] + b1b2[i];
}

// ---------------- embedding gather (fp16 out) ----------------
__global__ void embed_kernel(const int* __restrict__ tok, const float* __restrict__ ew) {
    int sb = blockIdx.x;
    int s = sb >> 4, b = sb & 15;
    int t = tok[b * Ss + s];
    float4 v = reinterpret_cast<const float4*>(ew + (size_t)t * Ee)[threadIdx.x];
    __half2* dst = reinterpret_cast<__half2*>(g_x0h + (size_t)sb * Ee);
    dst[2 * threadIdx.x]     = __floats2half2_rn(v.x, v.y);
    dst[2 * threadIdx.x + 1] = __floats2half2_rn(v.z, v.w);
}

// ================= persistent LSTM: 32 blocks/dir, 256 thr, mma recurrence ==========
// (R14 configuration — measured best: 357 us/layer)
#define WS16_B (64 * 520 * 2)              // 66560
#define HS16_B (16 * 520 * 2)              // 16640
#define ZR_OFF (WS16_B + HS16_B)           // 83200
#define LSTM_DSM (ZR_OFF + 64 * 16 * 4)    // 87296

__global__ __launch_bounds__(256) void lstm_persist(
    const float* __restrict__ Whh_f, const float* __restrict__ Whh_b, int mode)
{
    extern __shared__ char sm[];
    __half* ws16 = reinterpret_cast<__half*>(sm);
    float* zr = reinterpret_cast<float*>(sm + ZR_OFF);
    int dir = blockIdx.y;
    int u0 = blockIdx.x << 4;
    int tid = threadIdx.x;
    int wid = tid >> 5, lane = tid & 31;
    int gr = lane >> 2, gc = lane & 3;
    int gb = tid >> 4, gu = tid & 15;          // gate thread <-> (batch, unit)
    const float* Whh = dir ? Whh_b : Whh_f;
    uint32_t ws_b = smem_u32(sm);
    uint32_t hs_b = ws_b + WS16_B;

    // stage Whh chunk (fp32->fp16): local row r = gate*16 + ui
    for (int f4 = tid; f4 < 64 * 128; f4 += 256) {
        int r = f4 >> 7, c4 = f4 & 127;
        int R = (r >> 4) * Hh + u0 + (r & 15);
        float4 v = *reinterpret_cast<const float4*>(Whh + (size_t)R * Hh + (c4 << 2));
        __half2* d = reinterpret_cast<__half2*>(ws16 + r * 520 + (c4 << 2));
        d[0] = __floats2half2_rn(v.x, v.y);
        d[1] = __floats2half2_rn(v.z, v.w);
    }
    __syncthreads();

    // B-fragments for this warp's 8 gate-rows, all K=512
    uint32_t wreg[16][4];
    {
        int rl = (wid >> 1) * 16 + (wid & 1) * 8 + (lane & 7);
        uint32_t wrow = ws_b + (uint32_t)(rl * 1040 + (lane >> 3) * 16);
#pragma unroll
        for (int ks = 0; ks < 16; ks++)
            ldsm_x4(wreg[ks], wrow + (uint32_t)(ks * 64));
    }
    __syncthreads();

    uint32_t a_base = hs_b + (uint32_t)((lane & 15) * 1040 + (lane >> 4) * 16);
    float creg = 0.f;
    unsigned fbase = g_flags[dir][blockIdx.x][0];
    int zrow = (wid >> 1) * 16 + (wid & 1) * 8 + 2 * gc;
    const float* xg_base = g_xg[dir];

    for (int t = 0; t < Ss; t++) {
        int tidx = dir ? (Ss - 1 - t) : t;

        // prefetch xg for this step (overlaps the barrier wait below)
        const float* xgd = xg_base + (size_t)(tidx * Bb + gb) * G4 + (u0 + gu);
        float x0 = xgd[0], x1 = xgd[Hh], x2 = xgd[2 * Hh], x3 = xgd[3 * Hh];

        // wait: all 32 blocks of this dir finished step t-1
        if (t > 0) {
            if (wid == 0) {
                unsigned tgt = fbase + (unsigned)t;
                bool ok;
                do {
                    unsigned a = ld_acq(&g_flags[dir][lane][0]);
                    ok = ((int)(a - tgt) >= 0);
                } while (__ballot_sync(0xffffffffu, ok) != 0xffffffffu);
            }
            __syncthreads();
        }

        // stage h(t-1): 16 rows x 64 uint4
        {
            uint4* dst4 = reinterpret_cast<uint4*>(sm + WS16_B);
            if (t == 0) {
                uint4 z = make_uint4(0, 0, 0, 0);
#pragma unroll
                for (int jj = 0; jj < 4; jj++) {
                    int f = jj * 256 + tid;
                    dst4[(f >> 6) * 65 + (f & 63)] = z;
                }
            } else {
                const uint4* src4 = reinterpret_cast<const uint4*>(g_hh[t & 1][dir]);
#pragma unroll
                for (int jj = 0; jj < 4; jj++) {
                    int f = jj * 256 + tid;
                    dst4[(f >> 6) * 65 + (f & 63)] = __ldcv(src4 + f);
                }
            }
        }
        __syncthreads();

        // z = h @ Whh^T : two independent 16-deep mma chains
        float acc0[4] = {0.f, 0.f, 0.f, 0.f};
        float acc1[4] = {0.f, 0.f, 0.f, 0.f};
#pragma unroll
        for (int ks = 0; ks < 32; ks += 2) {
            uint32_t af[4], af2[4];
            ldsm_x4(af, a_base + (uint32_t)(ks * 32));
            mma_f16(acc0, af, wreg[ks >> 1][0], wreg[ks >> 1][1]);
            ldsm_x4(af2, a_base + (uint32_t)((ks + 1) * 32));
            mma_f16(acc1, af2, wreg[ks >> 1][2], wreg[ks >> 1][3]);
        }
        zr[zrow * 16 + gr]           = acc0[0] + acc1[0];
        zr[(zrow + 1) * 16 + gr]     = acc0[1] + acc1[1];
        zr[zrow * 16 + gr + 8]       = acc0[2] + acc1[2];
        zr[(zrow + 1) * 16 + gr + 8] = acc0[3] + acc1[3];
        __syncthreads();

        // gates: thread <-> (b=gb, unit=u0+gu)
        __half hh;
        {
            float zi = zr[(gu) * 16 + gb]      + x0;
            float zf = zr[(16 + gu) * 16 + gb] + x1;
            float zg = zr[(32 + gu) * 16 + gb] + x2;
            float zo = zr[(48 + gu) * 16 + gb] + x3;
            float ig = 1.f / (1.f + expf(-zi));
            float fg = 1.f / (1.f + expf(-zf));
            float gg = tanhf(zg);
            float og = 1.f / (1.f + expf(-zo));
            creg = fg * creg + ig * gg;
            float h = og * tanhf(creg);
            hh = __float2half_rn(h);
            g_hh[(t & 1) ^ 1][dir][gb * Hh + u0 + gu] = hh;
        }
        __syncthreads();

        // release
        if (tid == 0)
            asm volatile("st.release.gpu.global.u32 [%0], %1;"
                         :: "l"(&g_flags[dir][blockIdx.x][0]),
                            "r"(fbase + (unsigned)(t + 1)) : "memory");

        // layer-output store (off critical path)
        if (mode == 0)
            g_x1h[(size_t)(tidx * Bb + gb) * 1024 + (dir << 9) + u0 + gu] = hh;
        else
            g_hfinh[(size_t)gb * (Ss * 1024) + tidx * 1024 + (dir << 9) + u0 + gu] = hh;
    }
}

// ---------------- launch ----------------
extern "C" void kernel_launch(void* const* d_in, const int* in_sizes, int n_in,
                              void* d_out, int out_size)
{
    const int*   tok  = (const int*)d_in[0];
    const float* ew   = (const float*)d_in[1];
    const float* Wih0f = (const float*)d_in[2],  *Whh0f = (const float*)d_in[3];
    const float* bih0f = (const float*)d_in[4],  *bhh0f = (const float*)d_in[5];
    const float* Wih0b = (const float*)d_in[6],  *Whh0b = (const float*)d_in[7];
    const float* bih0b = (const float*)d_in[8],  *bhh0b = (const float*)d_in[9];
    const float* Wih1f = (const float*)d_in[10], *Whh1f = (const float*)d_in[11];
    const float* bih1f = (const float*)d_in[12], *bhh1f = (const float*)d_in[13];
    const float* Wih1b = (const float*)d_in[14], *Whh1b = (const float*)d_in[15];
    const float* bih1b = (const float*)d_in[16], *bhh1b = (const float*)d_in[17];
    const float* linw = (const float*)d_in[18],  *linb  = (const float*)d_in[19];
    float* out = (float*)d_out;

    __half *px0, *px1, *phf;
    float *pxg, *pbias;
    cudaGetSymbolAddress((void**)&px0, g_x0h);
    cudaGetSymbolAddress((void**)&px1, g_x1h);
    cudaGetSymbolAddress((void**)&pxg, g_xg);
    cudaGetSymbolAddress((void**)&phf, g_hfinh);
    cudaGetSymbolAddress((void**)&pbias, g_bias2);

    cudaFuncSetAttribute(gemm_mma, cudaFuncAttributeMaxDynamicSharedMemorySize, GEMM_DSM);
    cudaFuncSetAttribute(lstm_persist, cudaFuncAttributeMaxDynamicSharedMemorySize, LSTM_DSM);

    embed_kernel<<<MBr, 128>>>(tok, ew);
    bias_comb2<<<8, 256>>>(bih0f, bhh0f, bih0b, bhh0b, bih1f, bhh1f, bih1b, bhh1b);

    // ---- layer 0 ----
    gemm_mma<<<dim3(16, 32), 256, GEMM_DSM>>>(px0, Wih0f, Wih0b, pbias, pxg, 512, 0);
    lstm_persist<<<dim3(32, 2), 256, LSTM_DSM>>>(Whh0f, Whh0b, 0);

    // ---- layer 1 ----
    gemm_mma<<<dim3(16, 32), 256, GEMM_DSM>>>(px1, Wih1f, Wih1b, pbias + 4096, pxg, 1024, 0);
    lstm_persist<<<dim3(32, 2), 256, LSTM_DSM>>>(Whh1f, Whh1b, 1);

    // ---- final projection (lin_w fp32 read directly) ----
    gemm_mma<<<dim3(16, 250), 256, GEMM_DSM>>>(phf, linw, linw, linb, out, 1024, 1);
}

// round 17
// speedup vs baseline: 1.2440x; 1.0380x over previous
#include <cuda_runtime.h>
#include <cuda_fp16.h>
#include <math.h>
#include <stdint.h>

#define Vv  32000
#define Ee  512
#define Hh  512
#define Bb  16
#define Ss  128
#define G4  2048   // 4*H
#define MBr 2048   // S*B rows

// ---------------- scratch (static device memory; no allocation) ----------------
__device__ __half g_x0h[(size_t)MBr * Ee];        // layer0 input (fp16)
__device__ __half g_x1h[(size_t)MBr * 1024];      // layer1 input (fp16)
__device__ float  g_xg[2][(size_t)MBr * G4];      // per-dir gate preacts (fp32)
__device__ __half g_hh[2][2][Bb * Hh];            // [parity][dir][b*H] (fp16)
__device__ __half g_hfinh[(size_t)Bb * Ss * 1024];// layer1 output (fp16)
__device__ float  g_bias2[2][4096];               // combined bih+bhh per layer
__device__ unsigned g_flags[2][32][32];           // per-block step flags, 128B lines

// ================= helpers =================
__device__ __forceinline__ uint32_t smem_u32(const void* p) {
    uint32_t a;
    asm("{ .reg .u64 t; cvta.to.shared.u64 t, %1; cvt.u32.u64 %0, t; }" : "=r"(a) : "l"(p));
    return a;
}
__device__ __forceinline__ void cp16(uint32_t dst, const void* src) {
    asm volatile("cp.async.cg.shared.global [%0], [%1], 16;" :: "r"(dst), "l"(src) : "memory");
}
__device__ __forceinline__ void ldsm_x4(uint32_t* r, uint32_t addr) {
    asm volatile("ldmatrix.sync.aligned.m8n8.x4.shared.b16 {%0,%1,%2,%3}, [%4];"
                 : "=r"(r[0]), "=r"(r[1]), "=r"(r[2]), "=r"(r[3]) : "r"(addr));
}
__device__ __forceinline__ void mma_f16(float* c, const uint32_t* a, uint32_t b0, uint32_t b1) {
    asm volatile(
        "mma.sync.aligned.m16n8k16.row.col.f32.f16.f16.f32 "
        "{%0,%1,%2,%3}, {%4,%5,%6,%7}, {%8,%9}, {%0,%1,%2,%3};\n"
        : "+f"(c[0]), "+f"(c[1]), "+f"(c[2]), "+f"(c[3])
        : "r"(a[0]), "r"(a[1]), "r"(a[2]), "r"(a[3]), "r"(b0), "r"(b1));
}
__device__ __forceinline__ unsigned ld_acq(unsigned* p) {
    unsigned v;
    asm volatile("ld.acquire.gpu.global.u32 %0, [%1];" : "=r"(v) : "l"(p) : "memory");
    return v;
}
__device__ __forceinline__ float sig_fast(float x) {
    float r;
    asm("{\n\t.reg .f32 t;\n\t"
        "mul.f32 t, %1, 0fBFB8AA3B;\n\t"     // t = -x*log2(e)
        "ex2.approx.f32 t, t;\n\t"           // t = 2^t = e^-x
        "add.f32 t, t, 0f3F800000;\n\t"      // t = 1 + e^-x
        "rcp.approx.f32 %0, t;\n\t}"
        : "=f"(r) : "f"(x));
    return r;
}
__device__ __forceinline__ float tanh_fast(float x) {
    float r;
    asm("tanh.approx.f32 %0, %1;" : "=f"(r) : "f"(x));
    return r;
}

// ================= fp16 mma GEMM with fused fp32->fp16 B conversion =================
#define RSTR 80                    // bytes per smem row (32 halves + 8 pad)
#define ASTG (128 * RSTR)          // 10240 per A stage
#define BBASE (3 * ASTG)           // B stages start at 30720
#define GEMM_DSM 67584             // max(6*10240=61440, epilogue 128*132*4=67584)

__global__ __launch_bounds__(256, 2) void gemm_mma(
    const __half* __restrict__ A,
    const float* __restrict__ Bf32a, const float* __restrict__ Bf32b,
    const float* __restrict__ bias, float* __restrict__ out,
    int Kdim, int mode)
{
    extern __shared__ char dsmc[];
    float* dsm = reinterpret_cast<float*>(dsmc);
    int tid = threadIdx.x, wid = tid >> 5, lane = tid & 31;
    int warp_m = wid & 1, warp_n = wid >> 1;
    int gr = lane >> 2, gc = lane & 3;
    int m0 = blockIdx.x << 7;
    int n0 = blockIdx.y << 7;
    uint32_t base = smem_u32(dsmc);
    int KC = Kdim >> 5;

    const __half* Ag = A + (size_t)m0 * Kdim;
    const float* Bg = (mode == 0 && n0 >= 2048)
                    ? Bf32b + (size_t)(n0 - 2048) * Kdim
                    : Bf32a + (size_t)n0 * Kdim;

    int brow0 = tid >> 3, bg = tid & 7;
    const float* Bp = Bg + (size_t)brow0 * Kdim + bg * 4;

    uint32_t aoff = (uint32_t)((lane & 15) * RSTR + (lane >> 4) * 16)
                  + (uint32_t)(warp_m * 64 * RSTR);
    uint32_t boff = (uint32_t)(((lane & 7) + ((lane >> 3) & 1) * 8) * RSTR + (lane >> 4) * 16)
                  + (uint32_t)(warp_n * 32 * RSTR);

    float acc[4][4][4];
#pragma unroll
    for (int mi = 0; mi < 4; mi++)
#pragma unroll
        for (int ni = 0; ni < 4; ni++)
#pragma unroll
            for (int q = 0; q < 4; q++) acc[mi][ni][q] = 0.f;

#define LOAD_A(s, c) do {                                                   \
        uint32_t sb_ = base + (s) * ASTG;                                   \
        const __half* Ac_ = Ag + (c) * 32;                                  \
        _Pragma("unroll")                                                   \
        for (int q_ = 0; q_ < 2; q_++) {                                    \
            int f_ = q_ * 256 + tid;                                        \
            int row_ = f_ >> 2, g_ = f_ & 3;                                \
            cp16(sb_ + row_ * RSTR + g_ * 16,                               \
                 Ac_ + (size_t)row_ * Kdim + g_ * 8);                       \
        }                                                                   \
        asm volatile("cp.async.commit_group;" ::: "memory");                \
    } while (0)

#define STS_B(s, v) do {                                                    \
        char* bs_ = dsmc + BBASE + (s) * ASTG;                              \
        _Pragma("unroll")                                                   \
        for (int k_ = 0; k_ < 4; k_++) {                                    \
            __half2* d_ = reinterpret_cast<__half2*>(                       \
                bs_ + (brow0 + k_ * 32) * RSTR + bg * 8);                   \
            d_[0] = __floats2half2_rn((v)[k_].x, (v)[k_].y);                \
            d_[1] = __floats2half2_rn((v)[k_].z, (v)[k_].w);                \
        }                                                                   \
    } while (0)

#define LDG_B(c, v) do {                                                    \
        const float* p_ = Bp + (c) * 32;                                    \
        _Pragma("unroll")                                                   \
        for (int k_ = 0; k_ < 4; k_++)                                      \
            (v)[k_] = *reinterpret_cast<const float4*>(p_ + (size_t)(k_ * 32) * Kdim); \
    } while (0)

    LOAD_A(0, 0);
    LOAD_A(1, 1);
    LOAD_A(2, 2);
    {
        float4 v[4];
#pragma unroll
        for (int c = 0; c < 3; c++) { LDG_B(c, v); STS_B(c, v); }
    }
    float4 bb[4];
    LDG_B(3, bb);

    int s = 0;
    for (int c = 0; c < KC; c++) {
        asm volatile("cp.async.wait_group 2;" ::: "memory");
        __syncthreads();
        uint32_t sa = base + s * ASTG;
        uint32_t sb = base + BBASE + s * ASTG;
#pragma unroll
        for (int kb = 0; kb < 64; kb += 32) {
            uint32_t af[4][4], bf[2][4];
#pragma unroll
            for (int mi = 0; mi < 4; mi++)
                ldsm_x4(af[mi], sa + aoff + (uint32_t)(mi * 16 * RSTR) + kb);
#pragma unroll
            for (int nj = 0; nj < 2; nj++)
                ldsm_x4(bf[nj], sb + boff + (uint32_t)(nj * 16 * RSTR) + kb);
#pragma unroll
            for (int mi = 0; mi < 4; mi++)
#pragma unroll
                for (int ni = 0; ni < 4; ni++)
                    mma_f16(acc[mi][ni], af[mi],
                            bf[ni >> 1][ni & 1], bf[ni >> 1][2 + (ni & 1)]);
        }
        __syncthreads();
        if (c + 3 < KC) {
            STS_B(s, bb);
            if (c + 4 < KC) LDG_B(c + 4, bb);
            LOAD_A(s, c + 3);
        } else {
            asm volatile("cp.async.commit_group;" ::: "memory");
        }
        s++; if (s == 3) s = 0;
    }
    asm volatile("cp.async.wait_group 0;" ::: "memory");
    __syncthreads();

    if (mode == 1) {
        float* es = dsm;  // 128 cols x stride 132
#pragma unroll
        for (int mi = 0; mi < 4; mi++) {
            int row = warp_m * 64 + mi * 16 + gr;
#pragma unroll
            for (int ni = 0; ni < 4; ni++) {
                int col = warp_n * 32 + ni * 8 + gc * 2;
                es[col * 132 + row]           = acc[mi][ni][0];
                es[(col + 1) * 132 + row]     = acc[mi][ni][1];
                es[col * 132 + row + 8]       = acc[mi][ni][2];
                es[(col + 1) * 132 + row + 8] = acc[mi][ni][3];
            }
        }
        __syncthreads();
        int bb2 = blockIdx.x;
        float* ob = out + (size_t)bb2 * Vv * Ss;
#pragma unroll 4
        for (int i = 0; i < 16; i++) {
            int f4 = i * 256 + tid;
            int rown = f4 >> 5;
            int c4 = f4 & 31;
            float4 v = *reinterpret_cast<const float4*>(es + rown * 132 + c4 * 4);
            float bv = bias[n0 + rown];
            v.x += bv; v.y += bv; v.z += bv; v.w += bv;
            *reinterpret_cast<float4*>(ob + (size_t)(n0 + rown) * Ss + c4 * 4) = v;
        }
    } else {
        int dirq = n0 >> 11;
        float* dst = out + (size_t)dirq * ((size_t)MBr * G4);
        int ncol0 = n0 & 2047;
#pragma unroll
        for (int mi = 0; mi < 4; mi++) {
            int row = m0 + warp_m * 64 + mi * 16 + gr;
#pragma unroll
            for (int ni = 0; ni < 4; ni++) {
                int nglob = n0 + warp_n * 32 + ni * 8 + gc * 2;
                int col = ncol0 + warp_n * 32 + ni * 8 + gc * 2;
                float bv0 = bias[nglob], bv1 = bias[nglob + 1];
                float2 v0 = make_float2(acc[mi][ni][0] + bv0, acc[mi][ni][1] + bv1);
                float2 v1 = make_float2(acc[mi][ni][2] + bv0, acc[mi][ni][3] + bv1);
                *reinterpret_cast<float2*>(dst + (size_t)row * G4 + col) = v0;
                *reinterpret_cast<float2*>(dst + (size_t)(row + 8) * G4 + col) = v1;
            }
        }
    }
#undef LOAD_A
#undef STS_B
#undef LDG_B
}

// ---------------- combined bias, both layers in one launch ----------------
__global__ void bias_comb2(const float* __restrict__ b0f1, const float* __restrict__ b0f2,
                           const float* __restrict__ b0b1, const float* __restrict__ b0b2,
                           const float* __restrict__ b1f1, const float* __restrict__ b1f2,
                           const float* __restrict__ b1b1, const float* __restrict__ b1b2) {
    int i = blockIdx.x * blockDim.x + threadIdx.x;   // 0..2047
    g_bias2[0][i]        = b0f1[i] + b0f2[i];
    g_bias2[0][2048 + i] = b0b1[i] + b0b2[i];
    g_bias2[1][i]        = b1f1[i] + b1f2[i];
    g_bias2[1][2048 + i] = b1b1[i] + b1b2[i];
}

// ---------------- embedding gather (fp16 out) ----------------
__global__ void embed_kernel(const int* __restrict__ tok, const float* __restrict__ ew) {
    int sb = blockIdx.x;
    int s = sb >> 4, b = sb & 15;
    int t = tok[b * Ss + s];
    float4 v = reinterpret_cast<const float4*>(ew + (size_t)t * Ee)[threadIdx.x];
    __half2* dst = reinterpret_cast<__half2*>(g_x0h + (size_t)sb * Ee);
    dst[2 * threadIdx.x]     = __floats2half2_rn(v.x, v.y);
    dst[2 * threadIdx.x + 1] = __floats2half2_rn(v.z, v.w);
}

// ================= persistent LSTM: 32 blocks/dir, 256 thr, mma recurrence ==========
#define WS16_B (64 * 520 * 2)              // 66560
#define HS16_B (16 * 520 * 2)              // 16640
#define ZR_OFF (WS16_B + HS16_B)           // 83200
#define LSTM_DSM (ZR_OFF + 64 * 16 * 4)    // 87296

__global__ __launch_bounds__(256) void lstm_persist(
    const float* __restrict__ Whh_f, const float* __restrict__ Whh_b, int mode)
{
    extern __shared__ char sm[];
    __half* ws16 = reinterpret_cast<__half*>(sm);
    float* zr = reinterpret_cast<float*>(sm + ZR_OFF);
    int dir = blockIdx.y;
    int u0 = blockIdx.x << 4;
    int tid = threadIdx.x;
    int wid = tid >> 5, lane = tid & 31;
    int gr = lane >> 2, gc = lane & 3;
    int gb = tid >> 4, gu = tid & 15;          // gate thread <-> (batch, unit)
    const float* Whh = dir ? Whh_b : Whh_f;
    uint32_t ws_b = smem_u32(sm);
    uint32_t hs_b = ws_b + WS16_B;

    // stage Whh chunk (fp32->fp16): local row r = gate*16 + ui
    for (int f4 = tid; f4 < 64 * 128; f4 += 256) {
        int r = f4 >> 7, c4 = f4 & 127;
        int R = (r >> 4) * Hh + u0 + (r & 15);
        float4 v = *reinterpret_cast<const float4*>(Whh + (size_t)R * Hh + (c4 << 2));
        __half2* d = reinterpret_cast<__half2*>(ws16 + r * 520 + (c4 << 2));
        d[0] = __floats2half2_rn(v.x, v.y);
        d[1] = __floats2half2_rn(v.z, v.w);
    }
    __syncthreads();

    // B-fragments for this warp's 8 gate-rows, all K=512
    uint32_t wreg[16][4];
    {
        int rl = (wid >> 1) * 16 + (wid & 1) * 8 + (lane & 7);
        uint32_t wrow = ws_b + (uint32_t)(rl * 1040 + (lane >> 3) * 16);
#pragma unroll
        for (int ks = 0; ks < 16; ks++)
            ldsm_x4(wreg[ks], wrow + (uint32_t)(ks * 64));
    }
    __syncthreads();

    uint32_t a_base = hs_b + (uint32_t)((lane & 15) * 1040 + (lane >> 4) * 16);
    float creg = 0.f;
    unsigned fbase = g_flags[dir][blockIdx.x][0];
    int zrow = (wid >> 1) * 16 + (wid & 1) * 8 + 2 * gc;
    const float* xg_base = g_xg[dir];

    for (int t = 0; t < Ss; t++) {
        int tidx = dir ? (Ss - 1 - t) : t;

        // prefetch xg for this step (overlaps the barrier wait below)
        const float* xgd = xg_base + (size_t)(tidx * Bb + gb) * G4 + (u0 + gu);
        float x0 = xgd[0], x1 = xgd[Hh], x2 = xgd[2 * Hh], x3 = xgd[3 * Hh];

        // wait: all 32 blocks of this dir finished step t-1
        if (t > 0) {
            if (wid == 0) {
                unsigned tgt = fbase + (unsigned)t;
                bool ok;
                do {
                    unsigned a = ld_acq(&g_flags[dir][lane][0]);
                    ok = ((int)(a - tgt) >= 0);
                } while (__ballot_sync(0xffffffffu, ok) != 0xffffffffu);
            }
            __syncthreads();
        }

        // stage h(t-1): 16 rows x 64 uint4
        {
            uint4* dst4 = reinterpret_cast<uint4*>(sm + WS16_B);
            if (t == 0) {
                uint4 z = make_uint4(0, 0, 0, 0);
#pragma unroll
                for (int jj = 0; jj < 4; jj++) {
                    int f = jj * 256 + tid;
                    dst4[(f >> 6) * 65 + (f & 63)] = z;
                }
            } else {
                const uint4* src4 = reinterpret_cast<const uint4*>(g_hh[t & 1][dir]);
#pragma unroll
                for (int jj = 0; jj < 4; jj++) {
                    int f = jj * 256 + tid;
                    dst4[(f >> 6) * 65 + (f & 63)] = __ldcv(src4 + f);
                }
            }
        }
        __syncthreads();

        // z = h @ Whh^T : four independent 8-deep mma chains
        float acc0[4] = {0.f, 0.f, 0.f, 0.f};
        float acc1[4] = {0.f, 0.f, 0.f, 0.f};
        float acc2[4] = {0.f, 0.f, 0.f, 0.f};
        float acc3[4] = {0.f, 0.f, 0.f, 0.f};
#pragma unroll
        for (int ks = 0; ks < 32; ks += 4) {
            uint32_t af[4], af2[4], af3[4], af4[4];
            ldsm_x4(af,  a_base + (uint32_t)(ks * 32));
            mma_f16(acc0, af,  wreg[ks >> 1][0], wreg[ks >> 1][1]);
            ldsm_x4(af2, a_base + (uint32_t)((ks + 1) * 32));
            mma_f16(acc1, af2, wreg[ks >> 1][2], wreg[ks >> 1][3]);
            ldsm_x4(af3, a_base + (uint32_t)((ks + 2) * 32));
            mma_f16(acc2, af3, wreg[(ks >> 1) + 1][0], wreg[(ks >> 1) + 1][1]);
            ldsm_x4(af4, a_base + (uint32_t)((ks + 3) * 32));
            mma_f16(acc3, af4, wreg[(ks >> 1) + 1][2], wreg[(ks >> 1) + 1][3]);
        }
        zr[zrow * 16 + gr]           = (acc0[0] + acc1[0]) + (acc2[0] + acc3[0]);
        zr[(zrow + 1) * 16 + gr]     = (acc0[1] + acc1[1]) + (acc2[1] + acc3[1]);
        zr[zrow * 16 + gr + 8]       = (acc0[2] + acc1[2]) + (acc2[2] + acc3[2]);
        zr[(zrow + 1) * 16 + gr + 8] = (acc0[3] + acc1[3]) + (acc2[3] + acc3[3]);
        __syncthreads();

        // gates: thread <-> (b=gb, unit=u0+gu)  -- MUFU approx nonlinearities
        __half hh;
        {
            float zi = zr[(gu) * 16 + gb]      + x0;
            float zf = zr[(16 + gu) * 16 + gb] + x1;
            float zg = zr[(32 + gu) * 16 + gb] + x2;
            float zo = zr[(48 + gu) * 16 + gb] + x3;
            float ig = sig_fast(zi);
            float fg = sig_fast(zf);
            float gg = tanh_fast(zg);
            float og = sig_fast(zo);
            creg = fg * creg + ig * gg;
            float h = og * tanh_fast(creg);
            hh = __float2half_rn(h);
            g_hh[(t & 1) ^ 1][dir][gb * Hh + u0 + gu] = hh;
        }
        __syncthreads();

        // release
        if (tid == 0)
            asm volatile("st.release.gpu.global.u32 [%0], %1;"
                         :: "l"(&g_flags[dir][blockIdx.x][0]),
                            "r"(fbase + (unsigned)(t + 1)) : "memory");

        // layer-output store (off critical path)
        if (mode == 0)
            g_x1h[(size_t)(tidx * Bb + gb) * 1024 + (dir << 9) + u0 + gu] = hh;
        else
            g_hfinh[(size_t)gb * (Ss * 1024) + tidx * 1024 + (dir << 9) + u0 + gu] = hh;
    }
}

// ---------------- launch ----------------
extern "C" void kernel_launch(void* const* d_in, const int* in_sizes, int n_in,
                              void* d_out, int out_size)
{
    const int*   tok  = (const int*)d_in[0];
    const float* ew   = (const float*)d_in[1];
    const float* Wih0f = (const float*)d_in[2],  *Whh0f = (const float*)d_in[3];
    const float* bih0f = (const float*)d_in[4],  *bhh0f = (const float*)d_in[5];
    const float* Wih0b = (const float*)d_in[6],  *Whh0b = (const float*)d_in[7];
    const float* bih0b = (const float*)d_in[8],  *bhh0b = (const float*)d_in[9];
    const float* Wih1f = (const float*)d_in[10], *Whh1f = (const float*)d_in[11];
    const float* bih1f = (const float*)d_in[12], *bhh1f = (const float*)d_in[13];
    const float* Wih1b = (const float*)d_in[14], *Whh1b = (const float*)d_in[15];
    const float* bih1b = (const float*)d_in[16], *bhh1b = (const float*)d_in[17];
    const float* linw = (const float*)d_in[18],  *linb  = (const float*)d_in[19];
    float* out = (float*)d_out;

    __half *px0, *px1, *phf;
    float *pxg, *pbias;
    cudaGetSymbolAddress((void**)&px0, g_x0h);
    cudaGetSymbolAddress((void**)&px1, g_x1h);
    cudaGetSymbolAddress((void**)&pxg, g_xg);
    cudaGetSymbolAddress((void**)&phf, g_hfinh);
    cudaGetSymbolAddress((void**)&pbias, g_bias2);

    cudaFuncSetAttribute(gemm_mma, cudaFuncAttributeMaxDynamicSharedMemorySize, GEMM_DSM);
    cudaFuncSetAttribute(lstm_persist, cudaFuncAttributeMaxDynamicSharedMemorySize, LSTM_DSM);

    embed_kernel<<<MBr, 128>>>(tok, ew);
    bias_comb2<<<8, 256>>>(bih0f, bhh0f, bih0b, bhh0b, bih1f, bhh1f, bih1b, bhh1b);

    // ---- layer 0 ----
    gemm_mma<<<dim3(16, 32), 256, GEMM_DSM>>>(px0, Wih0f, Wih0b, pbias, pxg, 512, 0);
    lstm_persist<<<dim3(32, 2), 256, LSTM_DSM>>>(Whh0f, Whh0b, 0);

    // ---- layer 1 ----
    gemm_mma<<<dim3(16, 32), 256, GEMM_DSM>>>(px1, Wih1f, Wih1b, pbias + 4096, pxg, 1024, 0);
    lstm_persist<<<dim3(32, 2), 256, LSTM_DSM>>>(Whh1f, Whh1b, 1);

    // ---- final projection (lin_w fp32 read directly) ----
    gemm_mma<<<dim3(16, 250), 256, GEMM_DSM>>>(phf, linw, linw, linb, out, 1024, 1);
}